// round 10
// baseline (speedup 1.0000x reference)
#include <cuda_runtime.h>

#define NMAX 16384
#define KNN  16
#define CDIM 64
#define NODES_PER_BLOCK 4

#define GRES 32                    // grid cells per axis
#define GC   (GRES * GRES * GRES)  // 32768 cells
#define GB   4.5f                  // grid covers [-GB, GB]^3
#define GINVH (GRES / (2.0f * GB))
#define MARGIN 2.0f
#define RCAP2 2.25f                // r^2 cap (outliers -> flagged -> fallback)
#define BUFCAP 64

#define FULLMASK 0xffffffffu
#define FINF __int_as_float(0x7f800000)

// ---- scratch (no allocation allowed) ----
__device__ float4     g_pos4[NMAX];         // orig order (fallback queries)
__device__ ulonglong2 g_pairA[NMAX / 2];    // packed candidates (fallback)
__device__ ulonglong2 g_pairB[NMAX / 2];
__device__ int    g_knn[NMAX * KNN];
__device__ int    g_flag[NMAX];
__device__ float  g_B[NMAX * CDIM];
__device__ float  g_C[NMAX * CDIM];
// grid structures
__device__ int    g_cellCnt[GC];
__device__ int    g_cellStart[GC + 1];
__device__ int    g_cellPtr[GC];
__device__ int    g_pcell[NMAX];
__device__ float4 g_spos4[NMAX];            // cell-sorted points
__device__ int    g_sid[NMAX];              // sorted -> orig index

// ---- packed f32x2 helpers ----
__device__ __forceinline__ unsigned long long pk2(float a, float b) {
    unsigned long long r;
    asm("mov.b64 %0, {%1, %2};" : "=l"(r) : "f"(a), "f"(b));
    return r;
}
__device__ __forceinline__ void upk2(unsigned long long v, float& a, float& b) {
    asm("mov.b64 {%0, %1}, %2;" : "=f"(a), "=f"(b) : "l"(v));
}
__device__ __forceinline__ unsigned long long fma2(unsigned long long a,
                                                   unsigned long long b,
                                                   unsigned long long c) {
    unsigned long long r;
    asm("fma.rn.f32x2 %0, %1, %2, %3;" : "=l"(r) : "l"(a), "l"(b), "l"(c));
    return r;
}
__device__ __forceinline__ unsigned long long mul2(unsigned long long a,
                                                   unsigned long long b) {
    unsigned long long r;
    asm("mul.rn.f32x2 %0, %1, %2;" : "=l"(r) : "l"(a), "l"(b));
    return r;
}
__device__ __forceinline__ unsigned long long add2(unsigned long long a,
                                                   unsigned long long b) {
    unsigned long long r;
    asm("add.rn.f32x2 %0, %1, %2;" : "=l"(r) : "l"(a), "l"(b));
    return r;
}

// predicated 64-bit store: @p st (no BSSY/BSYNC — ptxas won't predicate C++ if)
__device__ __forceinline__ void st_pred(unsigned long long* p,
                                        unsigned long long v, int pred) {
    asm volatile("{ .reg .pred q; setp.ne.s32 q, %2, 0; @q st.u64 [%0], %1; }"
                 :: "l"(p), "l"(v), "r"(pred) : "memory");
}

// analytic radius^2: expected #points within r = KNN*MARGIN for pos~N(0,I3)
__device__ __forceinline__ float knn_thr(float qw, int n) {
    const float c0 = (KNN * MARGIN * 3.0f) /
                     (4.0f * 3.14159265f * 0.06349364f * (float)n);
    float r3 = c0 * __expf(0.5f * qw);
    return __powf(r3, 0.6666667f);
}

__device__ __forceinline__ int cell1d(float v) {
    int c = (int)floorf((v + GB) * GINVH);
    return min(GRES - 1, max(0, c));
}

// ============================================================
// Kernel A: zero cell counters
// ============================================================
__global__ void zero_cells_kernel() {
    int i = blockIdx.x * blockDim.x + threadIdx.x;
    if (i < GC) g_cellCnt[i] = 0;
}

// ============================================================
// Kernel 0: pack pos (orig order + fallback pair layout) + bin count
// ============================================================
__global__ void pack_pos_kernel(const float* __restrict__ pos, int n) {
    int i = blockIdx.x * blockDim.x + threadIdx.x;
    if (i < n / 2) {
        int a = 2 * i, b = 2 * i + 1;
        float xa = pos[a * 3 + 0], ya = pos[a * 3 + 1], za = pos[a * 3 + 2];
        float xb = pos[b * 3 + 0], yb = pos[b * 3 + 1], zb = pos[b * 3 + 2];
        float wa = fmaf(xa, xa, fmaf(ya, ya, za * za));
        float wb = fmaf(xb, xb, fmaf(yb, yb, zb * zb));
        g_pos4[a] = make_float4(xa, ya, za, wa);
        g_pos4[b] = make_float4(xb, yb, zb, wb);
        g_pairA[i] = make_ulonglong2(pk2(xa, xb), pk2(ya, yb));
        g_pairB[i] = make_ulonglong2(pk2(za, zb), pk2(wa, wb));
        int ca = (cell1d(za) * GRES + cell1d(ya)) * GRES + cell1d(xa);
        int cb = (cell1d(zb) * GRES + cell1d(yb)) * GRES + cell1d(xb);
        g_pcell[a] = ca;
        g_pcell[b] = cb;
        atomicAdd(&g_cellCnt[ca], 1);
        atomicAdd(&g_cellCnt[cb], 1);
    }
}

// ============================================================
// Kernel B: exclusive prefix sum over GC cells (single block, 1024 thr)
// ============================================================
__global__ __launch_bounds__(1024)
void scan_cells_kernel() {
    __shared__ int sh[1024];
    const int t = threadIdx.x;
    const int base = t * (GC / 1024);          // 32 cells per thread
    int loc[GC / 1024];
    int s = 0;
#pragma unroll
    for (int i = 0; i < GC / 1024; i++) { loc[i] = s; s += g_cellCnt[base + i]; }
    sh[t] = s;
    __syncthreads();
    for (int d = 1; d < 1024; d <<= 1) {       // Hillis-Steele inclusive scan
        int v = (t >= d) ? sh[t - d] : 0;
        __syncthreads();
        sh[t] += v;
        __syncthreads();
    }
    int off = sh[t] - s;                       // exclusive prefix of totals
#pragma unroll
    for (int i = 0; i < GC / 1024; i++) {
        int v = off + loc[i];
        g_cellStart[base + i] = v;
        g_cellPtr[base + i]   = v;
    }
    if (t == 1023) g_cellStart[GC] = off + s;
}

// ============================================================
// Kernel C: scatter points into cell-sorted order
// ============================================================
__global__ void scatter_kernel(int n) {
    int i = blockIdx.x * blockDim.x + threadIdx.x;
    if (i < n) {
        int dst = atomicAdd(&g_cellPtr[g_pcell[i]], 1);
        g_spos4[dst] = g_pos4[i];
        g_sid[dst]   = i;
    }
}

// ============================================================
// Kernel 1a: grid KNN — thread per SORTED query. Scans only cells
// intersecting ball(q, r). Appends survivors via predicated @p st.
// Keys pack the ORIGINAL index in the low 32 bits so distance ties
// resolve to the lowest original index, exactly matching
// jax.lax.top_k semantics (this was the R9 bug: sorted-index ties).
// Exactness: ball fully scanned, so cnt>=16 => top-16 exact;
// else flag -> exact fallback.
// ============================================================
__global__ __launch_bounds__(128)
void knn_grid_kernel(int n) {
    const int s = blockIdx.x * blockDim.x + threadIdx.x;
    const float4 qp = g_spos4[s];

    float thr = fminf(knn_thr(qp.w, n), RCAP2);
    const float r = sqrtf(thr);

    const int lx = cell1d(qp.x - r), hx = cell1d(qp.x + r);
    const int ly = cell1d(qp.y - r), hy = cell1d(qp.y + r);
    const int lz = cell1d(qp.z - r), hz = cell1d(qp.z + r);

    unsigned long long buf[BUFCAP];
    int cnt = 0;

    for (int cz = lz; cz <= hz; cz++) {
        for (int cy = ly; cy <= hy; cy++) {
            const int rowb = (cz * GRES + cy) * GRES;
            int t0 = g_cellStart[rowb + lx];
            const int t1 = g_cellStart[rowb + hx + 1];
            for (int t = t0; t < t1; t++) {
                float4 p = g_spos4[t];
                int orig_j = g_sid[t];              // L1-hot
                float dot = fmaf(qp.x, p.x, fmaf(qp.y, p.y, qp.z * p.z));
                float d = fmaf(-2.0f, dot, qp.w + p.w);   // ref formula
                int pred = (d < thr) & (t != s);
                unsigned long long key =
                    ((unsigned long long)__float_as_uint(fmaxf(d, 0.0f)) << 32)
                    | (unsigned)orig_j;             // tie-break = orig index
                int slot = (cnt < BUFCAP) ? cnt : 0;
                st_pred(&buf[slot], key, pred & (cnt < BUFCAP));
                cnt += pred;
            }
        }
    }

    const int orig = g_sid[s];
    const int bad = (cnt < KNN) | (cnt > BUFCAP);
    g_flag[orig] = bad;
    if (!bad) {
        // select 16 smallest by (dist, orig index) == reference ordering
        for (int rr = 0; rr < KNN; rr++) {
            unsigned long long m = ~0ULL;
            int mi = 0;
            for (int t = 0; t < cnt; t++) {
                unsigned long long v = buf[t];
                if (v < m) { m = v; mi = t; }
            }
            buf[mi] = ~0ULL;
            g_knn[orig * KNN + rr] = (int)(m & 0xffffffffu);
        }
    }
}

// ============================================================
// Kernel 1b: exact fallback for flagged queries — warp per query,
// warp-distributed sorted top-16 (proven R4 insert).
// ============================================================
__device__ __forceinline__ void warp_insert(float dn, int jn,
                                            float& bd, int& bj,
                                            float& worst, int lane) {
    float bp = __shfl_up_sync(FULLMASK, bd, 1);
    int   ip = __shfl_up_sync(FULLMASK, bj, 1);
    unsigned gm = __ballot_sync(FULLMASK, (lane < KNN) && (bd > dn));
    int pos = __ffs(gm) - 1;            // gm != 0 since bd[15] > dn
    if (lane < KNN) {
        if (lane > pos)       { bd = bp; bj = ip; }
        else if (lane == pos) { bd = fmaxf(dn, 0.0f); bj = jn; }
    }
    worst = __shfl_sync(FULLMASK, bd, KNN - 1);
}

__global__ __launch_bounds__(256)
void knn_fallback_kernel(int n) {
    const int lane = threadIdx.x & 31;
    const int q    = blockIdx.x * 8 + (threadIdx.x >> 5);
    if (g_flag[q] == 0) return;       // warp-uniform

    const float4 qp = g_pos4[q];
    const unsigned long long qx2 = pk2(qp.x, qp.x);
    const unsigned long long qy2 = pk2(qp.y, qp.y);
    const unsigned long long qz2 = pk2(qp.z, qp.z);
    const unsigned long long qw2 = pk2(qp.w, qp.w);
    const unsigned long long M2  = pk2(-2.0f, -2.0f);

    float bd = FINF;
    int   bj = 0;
    float worst = FINF;

    for (int base = 0; base < n / 2; base += 32) {
        ulonglong2 A = g_pairA[base + lane];
        ulonglong2 B = g_pairB[base + lane];
        unsigned long long acc = mul2(qz2, B.x);
        acc = fma2(qy2, A.y, acc);
        acc = fma2(qx2, A.x, acc);
        unsigned long long dd = fma2(M2, acc, add2(qw2, B.y));
        float d0, d1;
        upk2(dd, d0, d1);

        unsigned m = __ballot_sync(FULLMASK, (d0 < worst) | (d1 < worst));
        while (m) {
            int src = __ffs(m) - 1;
            m &= m - 1;
            float e0 = __shfl_sync(FULLMASK, d0, src);
            float e1 = __shfl_sync(FULLMASK, d1, src);
            int   j0 = 2 * (base + src);
            if (e0 < worst && j0 != q)
                warp_insert(e0, j0, bd, bj, worst, lane);
            if (e1 < worst && j0 + 1 != q)
                warp_insert(e1, j0 + 1, bd, bj, worst, lane);
        }
    }

    if (lane < KNN)
        g_knn[q * KNN + lane] = bj;
}

// ============================================================
// Kernel 2: B = x @ W1b ; C = x @ (W1a - W1b) + b1  (4-node blocked)
// ============================================================
__global__ __launch_bounds__(256)
void feat_kernel(const float* __restrict__ x,
                 const float* __restrict__ W1,
                 const float* __restrict__ b1, int n) {
    int t   = blockIdx.x * blockDim.x + threadIdx.x;
    int grp = t >> 6;
    int d   = t & 63;
    int n0  = grp * 4;
    if (n0 >= n) return;

    const float* x0 = x + n0 * CDIM;
    float a0 = 0, a1 = 0, a2 = 0, a3 = 0;
    float b0 = 0, b1v = 0, b2v = 0, b3 = 0;
#pragma unroll 8
    for (int c = 0; c < CDIM; c++) {
        float wa = W1[c * CDIM + d];
        float wb = W1[(CDIM + c) * CDIM + d];
        float x0v = x0[c];
        float x1v = x0[CDIM + c];
        float x2v = x0[2 * CDIM + c];
        float x3v = x0[3 * CDIM + c];
        a0 = fmaf(x0v, wa, a0);  b0  = fmaf(x0v, wb, b0);
        a1 = fmaf(x1v, wa, a1);  b1v = fmaf(x1v, wb, b1v);
        a2 = fmaf(x2v, wa, a2);  b2v = fmaf(x2v, wb, b2v);
        a3 = fmaf(x3v, wa, a3);  b3  = fmaf(x3v, wb, b3);
    }
    float bias = b1[d];
    g_B[(n0 + 0) * CDIM + d] = b0;   g_C[(n0 + 0) * CDIM + d] = a0 - b0  + bias;
    g_B[(n0 + 1) * CDIM + d] = b1v;  g_C[(n0 + 1) * CDIM + d] = a1 - b1v + bias;
    g_B[(n0 + 2) * CDIM + d] = b2v;  g_C[(n0 + 2) * CDIM + d] = a2 - b2v + bias;
    g_B[(n0 + 3) * CDIM + d] = b3;   g_C[(n0 + 3) * CDIM + d] = a3 - b3  + bias;
}

// ============================================================
// Kernel 3: edge — e-outer, transposed g tile, prefetch pipeline (R8)
// ============================================================
#define GSTRIDE 20
__global__ __launch_bounds__(64)
void edge_kernel(const float* __restrict__ W2,
                 const float* __restrict__ b2,
                 float* __restrict__ out, int n) {
    __shared__ __align__(16) float gsT[2][CDIM][GSTRIDE];
    const int d = threadIdx.x;
    const float b2d = b2[d];
    const int n0 = blockIdx.x * NODES_PER_BLOCK;

    float bv[KNN];
    float cv;
    {
        const int4* jr = (const int4*)&g_knn[n0 * KNN];
        int4 j4[4];
#pragma unroll
        for (int v = 0; v < 4; v++) j4[v] = jr[v];
        const int* jv = (const int*)j4;
        cv = g_C[n0 * CDIM + d];
#pragma unroll
        for (int k = 0; k < KNN; k++)
            bv[k] = g_B[jv[k] * CDIM + d];
    }

    for (int i = 0; i < NODES_PER_BLOCK; i++) {
        const int buf = i & 1;
        const int nn  = n0 + i;

#pragma unroll
        for (int k2 = 0; k2 < KNN / 2; k2++) {
            float2 gg;
            gg.x = fmaxf(cv + bv[2 * k2],     0.0f);
            gg.y = fmaxf(cv + bv[2 * k2 + 1], 0.0f);
            *(float2*)&gsT[buf][d][2 * k2] = gg;
        }

        if (i + 1 < NODES_PER_BLOCK) {
            const int nn1 = nn + 1;
            const int4* jr = (const int4*)&g_knn[nn1 * KNN];
            int4 j4[4];
#pragma unroll
            for (int v = 0; v < 4; v++) j4[v] = jr[v];
            const int* jv = (const int*)j4;
            cv = g_C[nn1 * CDIM + d];
#pragma unroll
            for (int k = 0; k < KNN; k++)
                bv[k] = g_B[jv[k] * CDIM + d];
        }
        __syncthreads();

        unsigned long long acc[8];
#pragma unroll
        for (int j = 0; j < 8; j++) acc[j] = 0ULL;
#pragma unroll 8
        for (int e = 0; e < CDIM; e++) {
            float wv = W2[e * CDIM + d];
            unsigned long long w2 = pk2(wv, wv);
            const ulonglong2* gp = (const ulonglong2*)&gsT[buf][e][0];
            ulonglong2 Ga = gp[0];
            ulonglong2 Gb = gp[1];
            acc[0] = fma2(Ga.x, w2, acc[0]);
            acc[1] = fma2(Ga.y, w2, acc[1]);
            acc[2] = fma2(Gb.x, w2, acc[2]);
            acc[3] = fma2(Gb.y, w2, acc[3]);
            const ulonglong2* gq = (const ulonglong2*)&gsT[buf][e][8];
            ulonglong2 Gc = gq[0];
            ulonglong2 Gd = gq[1];
            acc[4] = fma2(Gc.x, w2, acc[4]);
            acc[5] = fma2(Gd.x, w2, acc[5]);
            acc[6] = fma2(Gc.y, w2, acc[6]);
            acc[7] = fma2(Gd.y, w2, acc[7]);
        }
        float m = -3.4e38f;
#pragma unroll
        for (int j = 0; j < 8; j++) {
            float lo, hi;
            upk2(acc[j], lo, hi);
            m = fmaxf(m, fmaxf(lo, hi));
        }
        out[nn * CDIM + d] = m + b2d;
    }
}

// ============================================================
extern "C" void kernel_launch(void* const* d_in, const int* in_sizes, int n_in,
                              void* d_out, int out_size) {
    const float* x   = (const float*)d_in[0];
    const float* pos = (const float*)d_in[1];
    const float* W1  = (const float*)d_in[2];
    const float* b1  = (const float*)d_in[3];
    const float* W2  = (const float*)d_in[4];
    const float* b2  = (const float*)d_in[5];
    float* out = (float*)d_out;

    int n = in_sizes[1] / 3;
    if (n > NMAX) n = NMAX;

    zero_cells_kernel<<<GC / 256, 256>>>();
    pack_pos_kernel<<<(n / 2 + 255) / 256, 256>>>(pos, n);
    scan_cells_kernel<<<1, 1024>>>();
    scatter_kernel<<<(n + 255) / 256, 256>>>(n);
    knn_grid_kernel<<<(n + 127) / 128, 128>>>(n);
    knn_fallback_kernel<<<n / 8, 256>>>(n);
    feat_kernel<<<(n * CDIM / 4 + 255) / 256, 256>>>(x, W1, b1, n);
    edge_kernel<<<n / NODES_PER_BLOCK, CDIM>>>(W2, b2, out, n);
}

// round 11
// speedup vs baseline: 1.5966x; 1.5966x over previous
#include <cuda_runtime.h>

#define NMAX 16384
#define KNN  16
#define CDIM 64
#define NODES_PER_BLOCK 4

#define GRES 32                    // grid cells per axis
#define GC   (GRES * GRES * GRES)  // 32768 cells
#define GB   4.5f                  // grid covers [-GB, GB]^3
#define GINVH (GRES / (2.0f * GB))
#define MARGIN 2.0f
#define RCAP2 2.25f                // r^2 cap (outliers -> flagged -> fallback)

#define FULLMASK 0xffffffffu
#define FINF __int_as_float(0x7f800000)

// ---- scratch (no allocation allowed) ----
__device__ float4     g_pos4[NMAX];         // orig order (fallback queries)
__device__ ulonglong2 g_pairA[NMAX / 2];    // packed candidates (fallback)
__device__ ulonglong2 g_pairB[NMAX / 2];
__device__ int    g_knn[NMAX * KNN];
__device__ int    g_flag[NMAX];
__device__ float  g_B[NMAX * CDIM];
__device__ float  g_C[NMAX * CDIM];
// grid structures
__device__ int    g_cellCnt[GC];
__device__ int    g_cellStart[GC + 1];
__device__ int    g_cellPtr[GC];
__device__ int    g_pcell[NMAX];
__device__ float4 g_spos4[NMAX];            // cell-sorted points
__device__ int    g_sid[NMAX];              // sorted -> orig index

// ---- packed f32x2 helpers ----
__device__ __forceinline__ unsigned long long pk2(float a, float b) {
    unsigned long long r;
    asm("mov.b64 %0, {%1, %2};" : "=l"(r) : "f"(a), "f"(b));
    return r;
}
__device__ __forceinline__ void upk2(unsigned long long v, float& a, float& b) {
    asm("mov.b64 {%0, %1}, %2;" : "=f"(a), "=f"(b) : "l"(v));
}
__device__ __forceinline__ unsigned long long fma2(unsigned long long a,
                                                   unsigned long long b,
                                                   unsigned long long c) {
    unsigned long long r;
    asm("fma.rn.f32x2 %0, %1, %2, %3;" : "=l"(r) : "l"(a), "l"(b), "l"(c));
    return r;
}
__device__ __forceinline__ unsigned long long mul2(unsigned long long a,
                                                   unsigned long long b) {
    unsigned long long r;
    asm("mul.rn.f32x2 %0, %1, %2;" : "=l"(r) : "l"(a), "l"(b));
    return r;
}
__device__ __forceinline__ unsigned long long add2(unsigned long long a,
                                                   unsigned long long b) {
    unsigned long long r;
    asm("add.rn.f32x2 %0, %1, %2;" : "=l"(r) : "l"(a), "l"(b));
    return r;
}

// analytic radius^2: expected #points within r = KNN*MARGIN for pos~N(0,I3)
__device__ __forceinline__ float knn_thr(float qw, int n) {
    const float c0 = (KNN * MARGIN * 3.0f) /
                     (4.0f * 3.14159265f * 0.06349364f * (float)n);
    float r3 = c0 * __expf(0.5f * qw);
    return __powf(r3, 0.6666667f);
}

__device__ __forceinline__ int cell1d(float v) {
    int c = (int)floorf((v + GB) * GINVH);
    return min(GRES - 1, max(0, c));
}

// ============================================================
// Kernel A: zero cell counters
// ============================================================
__global__ void zero_cells_kernel() {
    int i = blockIdx.x * blockDim.x + threadIdx.x;
    if (i < GC) g_cellCnt[i] = 0;
}

// ============================================================
// Kernel 0: pack pos (orig order + fallback pair layout) + bin count
// ============================================================
__global__ void pack_pos_kernel(const float* __restrict__ pos, int n) {
    int i = blockIdx.x * blockDim.x + threadIdx.x;
    if (i < n / 2) {
        int a = 2 * i, b = 2 * i + 1;
        float xa = pos[a * 3 + 0], ya = pos[a * 3 + 1], za = pos[a * 3 + 2];
        float xb = pos[b * 3 + 0], yb = pos[b * 3 + 1], zb = pos[b * 3 + 2];
        float wa = fmaf(xa, xa, fmaf(ya, ya, za * za));
        float wb = fmaf(xb, xb, fmaf(yb, yb, zb * zb));
        g_pos4[a] = make_float4(xa, ya, za, wa);
        g_pos4[b] = make_float4(xb, yb, zb, wb);
        g_pairA[i] = make_ulonglong2(pk2(xa, xb), pk2(ya, yb));
        g_pairB[i] = make_ulonglong2(pk2(za, zb), pk2(wa, wb));
        int ca = (cell1d(za) * GRES + cell1d(ya)) * GRES + cell1d(xa);
        int cb = (cell1d(zb) * GRES + cell1d(yb)) * GRES + cell1d(xb);
        g_pcell[a] = ca;
        g_pcell[b] = cb;
        atomicAdd(&g_cellCnt[ca], 1);
        atomicAdd(&g_cellCnt[cb], 1);
    }
}

// ============================================================
// Kernel B: exclusive prefix sum over GC cells (single block, 1024 thr)
// ============================================================
__global__ __launch_bounds__(1024)
void scan_cells_kernel() {
    __shared__ int sh[1024];
    const int t = threadIdx.x;
    const int base = t * (GC / 1024);          // 32 cells per thread
    int loc[GC / 1024];
    int s = 0;
#pragma unroll
    for (int i = 0; i < GC / 1024; i++) { loc[i] = s; s += g_cellCnt[base + i]; }
    sh[t] = s;
    __syncthreads();
    for (int d = 1; d < 1024; d <<= 1) {       // Hillis-Steele inclusive scan
        int v = (t >= d) ? sh[t - d] : 0;
        __syncthreads();
        sh[t] += v;
        __syncthreads();
    }
    int off = sh[t] - s;                       // exclusive prefix of totals
#pragma unroll
    for (int i = 0; i < GC / 1024; i++) {
        int v = off + loc[i];
        g_cellStart[base + i] = v;
        g_cellPtr[base + i]   = v;
    }
    if (t == 1023) g_cellStart[GC] = off + s;
}

// ============================================================
// Kernel C: scatter points into cell-sorted order
// ============================================================
__global__ void scatter_kernel(int n) {
    int i = blockIdx.x * blockDim.x + threadIdx.x;
    if (i < n) {
        int dst = atomicAdd(&g_cellPtr[g_pcell[i]], 1);
        g_spos4[dst] = g_pos4[i];
        g_sid[dst]   = i;
    }
}

// ============================================================
// Kernel 1a: grid KNN — WARP per sorted query. Box bounds and row-runs
// are warp-uniform; lanes stride each run; gathers L1/L2-hot (adjacent
// warps scan overlapping cells). Top-16 is a warp-distributed sorted
// list of PACKED u64 keys (dist_bits<<32 | orig_idx): all comparisons
// are on keys, so distance ties resolve to lowest original index ==
// jax.lax.top_k semantics (R9 lesson). Seeded with the analytic
// threshold (R8 lesson) so only ~30 insert events fire per query.
// Exactness: ball fully scanned; key[15] >= seed => <16 in-ball
// survivors => flag -> exact fallback. No local memory anywhere.
// ============================================================
__device__ __forceinline__ void warp_insert64(unsigned long long kn,
                                              unsigned long long& bk,
                                              unsigned long long& worst,
                                              unsigned long long seed,
                                              int lane) {
    unsigned long long bp = __shfl_up_sync(FULLMASK, bk, 1);
    unsigned gm = __ballot_sync(FULLMASK, (lane < KNN) && (bk > kn));
    int pos = __ffs(gm) - 1;            // gm != 0 since bk[15] > kn
    if (lane < KNN) {
        if (lane > pos)       bk = bp;
        else if (lane == pos) bk = kn;
    }
    worst = min(seed, __shfl_sync(FULLMASK, bk, KNN - 1));
}

__global__ __launch_bounds__(256)
void knn_grid_kernel(int n) {
    const int w    = threadIdx.x >> 5;
    const int lane = threadIdx.x & 31;
    const int s    = blockIdx.x * 8 + w;       // sorted query index

    const float4 qp = g_spos4[s];
    const float thr = fminf(knn_thr(qp.w, n), RCAP2);
    const float r   = sqrtf(thr);

    const int lx = cell1d(qp.x - r), hx = cell1d(qp.x + r);
    const int ly = cell1d(qp.y - r), hy = cell1d(qp.y + r);
    const int lz = cell1d(qp.z - r), hz = cell1d(qp.z + r);

    const unsigned long long seed =
        ((unsigned long long)__float_as_uint(thr)) << 32;
    unsigned long long bk = ~0ULL;     // rank `lane` of sorted top-16 keys
    unsigned long long worst = seed;   // warp-uniform

    for (int cz = lz; cz <= hz; cz++) {
        for (int cy = ly; cy <= hy; cy++) {
            const int rowb = (cz * GRES + cy) * GRES;
            const int t0 = g_cellStart[rowb + lx];     // uniform (L1 bcast)
            const int t1 = g_cellStart[rowb + hx + 1];
            for (int tb = t0; tb < t1; tb += 32) {
                const int t  = tb + lane;
                const int tc = min(t, n - 1);
                float4 p = g_spos4[tc];
                int   oj = g_sid[tc];
                float dot = fmaf(qp.x, p.x, fmaf(qp.y, p.y, qp.z * p.z));
                float d = fmaf(-2.0f, dot, qp.w + p.w);   // ref formula
                unsigned long long key =
                    (((unsigned long long)__float_as_uint(fmaxf(d, 0.0f))) << 32)
                    | (unsigned)oj;
                bool valid = (t < t1) && (t != s) && (key < worst);
                unsigned m = __ballot_sync(FULLMASK, valid);
                while (m) {                    // warp-uniform event loop
                    int src = __ffs(m) - 1;
                    m &= m - 1;
                    unsigned long long kn = __shfl_sync(FULLMASK, key, src);
                    if (kn < worst)            // uniform (worst tightens)
                        warp_insert64(kn, bk, worst, seed, lane);
                }
            }
        }
    }

    const int orig = g_sid[s];
    // certificate: 16 real survivors inside the fully-scanned ball?
    unsigned long long k15 = __shfl_sync(FULLMASK, bk, KNN - 1);
    if (lane == 0) g_flag[orig] = (k15 >= seed);
    if (lane < KNN)
        g_knn[orig * KNN + lane] = (int)(bk & 0xffffffffu);
}

// ============================================================
// Kernel 1b: exact fallback for flagged queries — warp per query,
// warp-distributed sorted top-16 over ALL candidates (key-based, so
// tie-break is exact here too).
// ============================================================
__global__ __launch_bounds__(256)
void knn_fallback_kernel(int n) {
    const int lane = threadIdx.x & 31;
    const int q    = blockIdx.x * 8 + (threadIdx.x >> 5);
    if (g_flag[q] == 0) return;       // warp-uniform

    const float4 qp = g_pos4[q];
    const unsigned long long qx2 = pk2(qp.x, qp.x);
    const unsigned long long qy2 = pk2(qp.y, qp.y);
    const unsigned long long qz2 = pk2(qp.z, qp.z);
    const unsigned long long qw2 = pk2(qp.w, qp.w);
    const unsigned long long M2  = pk2(-2.0f, -2.0f);

    const unsigned long long seed = ~0ULL;
    unsigned long long bk = ~0ULL;
    unsigned long long worst = ~0ULL;

    for (int base = 0; base < n / 2; base += 32) {
        ulonglong2 A = g_pairA[base + lane];
        ulonglong2 B = g_pairB[base + lane];
        unsigned long long acc = mul2(qz2, B.x);
        acc = fma2(qy2, A.y, acc);
        acc = fma2(qx2, A.x, acc);
        unsigned long long dd = fma2(M2, acc, add2(qw2, B.y));
        float d0, d1;
        upk2(dd, d0, d1);
        int j0 = 2 * (base + lane);
        unsigned long long k0 =
            (((unsigned long long)__float_as_uint(fmaxf(d0, 0.0f))) << 32)
            | (unsigned)j0;
        unsigned long long k1 =
            (((unsigned long long)__float_as_uint(fmaxf(d1, 0.0f))) << 32)
            | (unsigned)(j0 + 1);
        bool v0 = (k0 < worst) && (j0 != q);
        bool v1 = (k1 < worst) && (j0 + 1 != q);

        unsigned m = __ballot_sync(FULLMASK, v0 | v1);
        while (m) {
            int src = __ffs(m) - 1;
            m &= m - 1;
            unsigned long long e0 = __shfl_sync(FULLMASK, k0, src);
            unsigned long long e1 = __shfl_sync(FULLMASK, k1, src);
            int jj = __shfl_sync(FULLMASK, j0, src);
            if (e0 < worst && jj != q)
                warp_insert64(e0, bk, worst, seed, lane);
            if (e1 < worst && jj + 1 != q)
                warp_insert64(e1, bk, worst, seed, lane);
        }
    }

    if (lane < KNN)
        g_knn[q * KNN + lane] = (int)(bk & 0xffffffffu);
}

// ============================================================
// Kernel 2: B = x @ W1b ; C = x @ (W1a - W1b) + b1  (4-node blocked)
// ============================================================
__global__ __launch_bounds__(256)
void feat_kernel(const float* __restrict__ x,
                 const float* __restrict__ W1,
                 const float* __restrict__ b1, int n) {
    int t   = blockIdx.x * blockDim.x + threadIdx.x;
    int grp = t >> 6;
    int d   = t & 63;
    int n0  = grp * 4;
    if (n0 >= n) return;

    const float* x0 = x + n0 * CDIM;
    float a0 = 0, a1 = 0, a2 = 0, a3 = 0;
    float b0 = 0, b1v = 0, b2v = 0, b3 = 0;
#pragma unroll 8
    for (int c = 0; c < CDIM; c++) {
        float wa = W1[c * CDIM + d];
        float wb = W1[(CDIM + c) * CDIM + d];
        float x0v = x0[c];
        float x1v = x0[CDIM + c];
        float x2v = x0[2 * CDIM + c];
        float x3v = x0[3 * CDIM + c];
        a0 = fmaf(x0v, wa, a0);  b0  = fmaf(x0v, wb, b0);
        a1 = fmaf(x1v, wa, a1);  b1v = fmaf(x1v, wb, b1v);
        a2 = fmaf(x2v, wa, a2);  b2v = fmaf(x2v, wb, b2v);
        a3 = fmaf(x3v, wa, a3);  b3  = fmaf(x3v, wb, b3);
    }
    float bias = b1[d];
    g_B[(n0 + 0) * CDIM + d] = b0;   g_C[(n0 + 0) * CDIM + d] = a0 - b0  + bias;
    g_B[(n0 + 1) * CDIM + d] = b1v;  g_C[(n0 + 1) * CDIM + d] = a1 - b1v + bias;
    g_B[(n0 + 2) * CDIM + d] = b2v;  g_C[(n0 + 2) * CDIM + d] = a2 - b2v + bias;
    g_B[(n0 + 3) * CDIM + d] = b3;   g_C[(n0 + 3) * CDIM + d] = a3 - b3  + bias;
}

// ============================================================
// Kernel 3: edge — e-outer, transposed g tile, prefetch pipeline (R8)
// ============================================================
#define GSTRIDE 20
__global__ __launch_bounds__(64)
void edge_kernel(const float* __restrict__ W2,
                 const float* __restrict__ b2,
                 float* __restrict__ out, int n) {
    __shared__ __align__(16) float gsT[2][CDIM][GSTRIDE];
    const int d = threadIdx.x;
    const float b2d = b2[d];
    const int n0 = blockIdx.x * NODES_PER_BLOCK;

    float bv[KNN];
    float cv;
    {
        const int4* jr = (const int4*)&g_knn[n0 * KNN];
        int4 j4[4];
#pragma unroll
        for (int v = 0; v < 4; v++) j4[v] = jr[v];
        const int* jv = (const int*)j4;
        cv = g_C[n0 * CDIM + d];
#pragma unroll
        for (int k = 0; k < KNN; k++)
            bv[k] = g_B[jv[k] * CDIM + d];
    }

    for (int i = 0; i < NODES_PER_BLOCK; i++) {
        const int buf = i & 1;
        const int nn  = n0 + i;

#pragma unroll
        for (int k2 = 0; k2 < KNN / 2; k2++) {
            float2 gg;
            gg.x = fmaxf(cv + bv[2 * k2],     0.0f);
            gg.y = fmaxf(cv + bv[2 * k2 + 1], 0.0f);
            *(float2*)&gsT[buf][d][2 * k2] = gg;
        }

        if (i + 1 < NODES_PER_BLOCK) {
            const int nn1 = nn + 1;
            const int4* jr = (const int4*)&g_knn[nn1 * KNN];
            int4 j4[4];
#pragma unroll
            for (int v = 0; v < 4; v++) j4[v] = jr[v];
            const int* jv = (const int*)j4;
            cv = g_C[nn1 * CDIM + d];
#pragma unroll
            for (int k = 0; k < KNN; k++)
                bv[k] = g_B[jv[k] * CDIM + d];
        }
        __syncthreads();

        unsigned long long acc[8];
#pragma unroll
        for (int j = 0; j < 8; j++) acc[j] = 0ULL;
#pragma unroll 8
        for (int e = 0; e < CDIM; e++) {
            float wv = W2[e * CDIM + d];
            unsigned long long w2 = pk2(wv, wv);
            const ulonglong2* gp = (const ulonglong2*)&gsT[buf][e][0];
            ulonglong2 Ga = gp[0];
            ulonglong2 Gb = gp[1];
            acc[0] = fma2(Ga.x, w2, acc[0]);
            acc[1] = fma2(Ga.y, w2, acc[1]);
            acc[2] = fma2(Gb.x, w2, acc[2]);
            acc[3] = fma2(Gb.y, w2, acc[3]);
            const ulonglong2* gq = (const ulonglong2*)&gsT[buf][e][8];
            ulonglong2 Gc = gq[0];
            ulonglong2 Gd = gq[1];
            acc[4] = fma2(Gc.x, w2, acc[4]);
            acc[5] = fma2(Gd.x, w2, acc[5]);
            acc[6] = fma2(Gc.y, w2, acc[6]);
            acc[7] = fma2(Gd.y, w2, acc[7]);
        }
        float m = -3.4e38f;
#pragma unroll
        for (int j = 0; j < 8; j++) {
            float lo, hi;
            upk2(acc[j], lo, hi);
            m = fmaxf(m, fmaxf(lo, hi));
        }
        out[nn * CDIM + d] = m + b2d;
    }
}

// ============================================================
extern "C" void kernel_launch(void* const* d_in, const int* in_sizes, int n_in,
                              void* d_out, int out_size) {
    const float* x   = (const float*)d_in[0];
    const float* pos = (const float*)d_in[1];
    const float* W1  = (const float*)d_in[2];
    const float* b1  = (const float*)d_in[3];
    const float* W2  = (const float*)d_in[4];
    const float* b2  = (const float*)d_in[5];
    float* out = (float*)d_out;

    int n = in_sizes[1] / 3;
    if (n > NMAX) n = NMAX;

    zero_cells_kernel<<<GC / 256, 256>>>();
    pack_pos_kernel<<<(n / 2 + 255) / 256, 256>>>(pos, n);
    scan_cells_kernel<<<1, 1024>>>();
    scatter_kernel<<<(n + 255) / 256, 256>>>(n);
    knn_grid_kernel<<<(n + 7) / 8, 256>>>(n);
    knn_fallback_kernel<<<n / 8, 256>>>(n);
    feat_kernel<<<(n * CDIM / 4 + 255) / 256, 256>>>(x, W1, b1, n);
    edge_kernel<<<n / NODES_PER_BLOCK, CDIM>>>(W2, b2, out, n);
}